// round 12
// baseline (speedup 1.0000x reference)
#include <cuda_runtime.h>
#include <cuda_bf16.h>
#include <cstdint>

#define HW   16384
#define CDIM 192
#define C3   576
#define BATCH 8
#define HEADS 8
#define CHD  24

typedef unsigned long long ull;

// ---------------- scratch (device globals: allocation-free rule) ----------------
__device__ __nv_bfloat16 g_xb [25165824];   // [8,192,16384] x in bf16 (for qk gemm)
__device__ __nv_bfloat16 g_wqkb[73728];     // [384,192] W_qkv rows 0..383 in bf16
__device__ float g_wvt [36864];             // [192,192] W_qkv v-rows, tf32-formatted
__device__ __nv_bfloat16 g_qkb[50331648];   // [8,384,16384] pre-conv q,k (bf16)
__device__ float g_vpre[25165824];          // [8,192,16384] pre-conv v (fp32)
__device__ __nv_bfloat16 g_qk[50331648];    // [8,384,16384] post-conv q,k (bf16)
__device__ float g_v  [25165824];           // [8,192,16384] post-conv v (fp32)
__device__ float g_var [BATCH*CDIM];
__device__ float g_norm[BATCH*384];
__device__ float g_S   [BATCH*HEADS*CHD*CHD];
__device__ float g_M   [BATCH*CDIM*CDIM];   // tf32-formatted by k_soft

__device__ __forceinline__ uint32_t smem_u32(const void* p) {
    uint32_t a;
    asm("{ .reg .u64 t; cvta.to.shared.u64 t, %1; cvt.u32.u64 %0, t; }" : "=r"(a) : "l"(p));
    return a;
}
__device__ __forceinline__ uint32_t f2tf32(float f) {
    uint32_t o;
    asm("cvt.rna.tf32.f32 %0, %1;" : "=r"(o) : "f"(f));
    return o;
}
// NOTE: mma / ldmatrix are intentionally NON-volatile: no side effects beyond
// register outputs; lets ptxas software-pipeline fragment loads across MMAs.
__device__ __forceinline__ void mma_tf32(float* c, const uint32_t* a, const uint32_t* b) {
    asm("mma.sync.aligned.m16n8k8.row.col.f32.tf32.tf32.f32 "
        "{%0,%1,%2,%3}, {%4,%5,%6,%7}, {%8,%9}, {%0,%1,%2,%3};"
        : "+f"(c[0]), "+f"(c[1]), "+f"(c[2]), "+f"(c[3])
        : "r"(a[0]), "r"(a[1]), "r"(a[2]), "r"(a[3]), "r"(b[0]), "r"(b[1]));
}
__device__ __forceinline__ void mma_bf16(float* c, const uint32_t* a, const uint32_t* b) {
    asm("mma.sync.aligned.m16n8k16.row.col.f32.bf16.bf16.f32 "
        "{%0,%1,%2,%3}, {%4,%5,%6,%7}, {%8,%9}, {%0,%1,%2,%3};"
        : "+f"(c[0]), "+f"(c[1]), "+f"(c[2]), "+f"(c[3])
        : "r"(a[0]), "r"(a[1]), "r"(a[2]), "r"(a[3]), "r"(b[0]), "r"(b[1]));
}
__device__ __forceinline__ void ldsm_x4(uint32_t* r, uint32_t addr) {
    asm("ldmatrix.sync.aligned.m8n8.x4.shared.b16 {%0,%1,%2,%3}, [%4];"
        : "=r"(r[0]), "=r"(r[1]), "=r"(r[2]), "=r"(r[3]) : "r"(addr));
}
__device__ __forceinline__ void ldsm_x4t(uint32_t* r, uint32_t addr) {
    asm("ldmatrix.sync.aligned.m8n8.x4.trans.shared.b16 {%0,%1,%2,%3}, [%4];"
        : "=r"(r[0]), "=r"(r[1]), "=r"(r[2]), "=r"(r[3]) : "r"(addr));
}
__device__ __forceinline__ void cp_async16(uint32_t dst, const void* src) {
    asm volatile("cp.async.cg.shared.global [%0], [%1], 16;" :: "r"(dst), "l"(src) : "memory");
}
__device__ __forceinline__ ull pack2(float a, float b) {
    ull r; asm("mov.b64 %0, {%1,%2};" : "=l"(r) : "f"(a), "f"(b)); return r;
}
__device__ __forceinline__ void ffma2(ull& acc, ull a, ull b) {
    asm("fma.rn.f32x2 %0, %1, %2, %0;" : "+l"(acc) : "l"(a), "l"(b));
}
__device__ __forceinline__ void add2(ull& acc, ull a) {
    asm("add.rn.f32x2 %0, %0, %1;" : "+l"(acc) : "l"(a));
}
__device__ __forceinline__ float2 unpack2(ull v) {
    float2 o; asm("mov.b64 {%0,%1}, %2;" : "=f"(o.x), "=f"(o.y) : "l"(v)); return o;
}

// ================= bf16 mma GEMM for q,k rows: C[384,HW] = A[384,192] @ B[192,HW] =================
// BM=64, BN=256, BK=32, 2-stage cp.async pipeline, 256 threads.
__global__ void __launch_bounds__(256, 2) gemm_bf16(
    const __nv_bfloat16* __restrict__ A,
    const __nv_bfloat16* __restrict__ B,
    __nv_bfloat16* __restrict__ C)
{
    __shared__ __nv_bfloat16 As[2][64][40];
    __shared__ __nv_bfloat16 Bs[2][32][264];
    const int tid = threadIdx.x, lane = tid & 31, wid = tid >> 5;
    const int g = lane >> 2, t = lane & 3;
    const int bm = blockIdx.x * 64, bn = blockIdx.y * 256;
    const __nv_bfloat16* Bb = B + (size_t)blockIdx.z * CDIM * HW;
    __nv_bfloat16* Cb = C + (size_t)blockIdx.z * 384 * HW;

    const int arow = tid >> 2, akc = (tid & 3) * 8;

    float acc[4][4][4];
    #pragma unroll
    for (int i = 0; i < 4; i++)
        #pragma unroll
        for (int j = 0; j < 4; j++)
            #pragma unroll
            for (int l = 0; l < 4; l++) acc[i][j][l] = 0.f;

    const int a_m = (lane & 15);
    const int a_k = ((lane >> 4) & 1) * 8;
    const int b_k = (lane & 7) + ((lane >> 3) & 1) * 8;
    const int b_n = wid * 32 + ((lane >> 4) & 1) * 8;

    cp_async16(smem_u32(&As[0][arow][akc]), &A[(size_t)(bm + arow) * 192 + akc]);
    #pragma unroll
    for (int p = 0; p < 4; p++) {
        int c = tid + p * 256;
        int kr = c >> 5, nc = (c & 31) * 8;
        cp_async16(smem_u32(&Bs[0][kr][nc]), &Bb[(size_t)kr * HW + bn + nc]);
    }
    asm volatile("cp.async.commit_group;" ::: "memory");
    asm volatile("cp.async.wait_group 0;" ::: "memory");
    __syncthreads();

    #pragma unroll 1
    for (int i = 0; i < 6; i++) {
        const int s = i & 1;
        if (i < 5) {
            const int k0 = (i + 1) * 32;
            cp_async16(smem_u32(&As[s ^ 1][arow][akc]), &A[(size_t)(bm + arow) * 192 + k0 + akc]);
            #pragma unroll
            for (int p = 0; p < 4; p++) {
                int c = tid + p * 256;
                int kr = c >> 5, nc = (c & 31) * 8;
                cp_async16(smem_u32(&Bs[s ^ 1][kr][nc]), &Bb[(size_t)(k0 + kr) * HW + bn + nc]);
            }
            asm volatile("cp.async.commit_group;" ::: "memory");
        }
        #pragma unroll
        for (int kk = 0; kk < 2; kk++) {
            uint32_t af[4][4];
            #pragma unroll
            for (int ma = 0; ma < 4; ma++)
                ldsm_x4(af[ma], smem_u32(&As[s][ma * 16 + a_m][kk * 16 + a_k]));
            uint32_t bf[4][4];
            #pragma unroll
            for (int p = 0; p < 2; p++)
                ldsm_x4t(bf[p], smem_u32(&Bs[s][kk * 16 + b_k][b_n + p * 16]));
            #pragma unroll
            for (int ma = 0; ma < 4; ma++) {
                #pragma unroll
                for (int p = 0; p < 2; p++) {
                    mma_bf16(acc[ma][p * 2 + 0], af[ma], &bf[p][0]);
                    mma_bf16(acc[ma][p * 2 + 1], af[ma], &bf[p][2]);
                }
            }
        }
        if (i < 5) asm volatile("cp.async.wait_group 0;" ::: "memory");
        __syncthreads();
    }
    #pragma unroll
    for (int ma = 0; ma < 4; ma++) {
        #pragma unroll
        for (int nt = 0; nt < 4; nt++) {
            const int row = bm + ma * 16 + g;
            const int col = bn + wid * 32 + (nt >> 1) * 16 + (nt & 1) * 8 + 2 * t;
            __nv_bfloat162 h0 = __floats2bfloat162_rn(acc[ma][nt][0], acc[ma][nt][1]);
            __nv_bfloat162 h1 = __floats2bfloat162_rn(acc[ma][nt][2], acc[ma][nt][3]);
            *(__nv_bfloat162*)&Cb[(size_t)row * HW + col]       = h0;
            *(__nv_bfloat162*)&Cb[(size_t)(row + 8) * HW + col] = h1;
        }
    }
}

// ================= tf32 mma.sync GEMM, BN=256, BK=32, A pre-converted to tf32 =================
__global__ void __launch_bounds__(256, 2) gemm_mma(
    const float* __restrict__ A, const float* __restrict__ B, float* __restrict__ C,
    int M, int N, int K, long long sA, long long sB, long long sC)
{
    __shared__ float As[2][64][36];
    __shared__ float Bs[2][32][264];
    const int tid  = threadIdx.x;
    const int lane = tid & 31;
    const int wid  = tid >> 5;
    const int g    = lane >> 2;
    const int t    = lane & 3;
    const float* Ab = A + (long long)blockIdx.z * sA;
    const float* Bb = B + (long long)blockIdx.z * sB;
    float*       Cb = C + (long long)blockIdx.z * sC;
    const int bm = blockIdx.x * 64;
    const int bn = blockIdx.y * 256;

    const int arow = tid >> 2;            // 0..63
    const int acol = (tid & 3) * 8;       // 0,8,16,24
    const int a_m = lane & 15;
    const int a_k = (lane >> 4) * 4;

    float acc[4][4][4];
    #pragma unroll
    for (int i = 0; i < 4; i++)
        #pragma unroll
        for (int j = 0; j < 4; j++)
            #pragma unroll
            for (int l = 0; l < 4; l++) acc[i][j][l] = 0.f;

    // ---- preload stage 0 (all cp.async) ----
    cp_async16(smem_u32(&As[0][arow][acol]),     &Ab[(size_t)(bm + arow) * K + acol]);
    cp_async16(smem_u32(&As[0][arow][acol + 4]), &Ab[(size_t)(bm + arow) * K + acol + 4]);
    #pragma unroll
    for (int p = 0; p < 8; p++) {
        int c = tid + p * 256;
        int kr = c >> 6, nc = (c & 63) * 4;
        cp_async16(smem_u32(&Bs[0][kr][nc]), &Bb[(size_t)kr * N + bn + nc]);
    }
    asm volatile("cp.async.commit_group;" ::: "memory");
    asm volatile("cp.async.wait_group 0;" ::: "memory");
    __syncthreads();

    const int nchunk = K >> 5;    // 6 for K=192
    #pragma unroll 1
    for (int i = 0; i < nchunk; i++) {
        const int s = i & 1;
        if (i + 1 < nchunk) {
            const int k0 = (i + 1) << 5;
            cp_async16(smem_u32(&As[s ^ 1][arow][acol]),     &Ab[(size_t)(bm + arow) * K + k0 + acol]);
            cp_async16(smem_u32(&As[s ^ 1][arow][acol + 4]), &Ab[(size_t)(bm + arow) * K + k0 + acol + 4]);
            #pragma unroll
            for (int p = 0; p < 8; p++) {
                int c = tid + p * 256;
                int kr = c >> 6, nc = (c & 63) * 4;
                cp_async16(smem_u32(&Bs[s ^ 1][kr][nc]), &Bb[(size_t)(k0 + kr) * N + bn + nc]);
            }
            asm volatile("cp.async.commit_group;" ::: "memory");
        }
        #pragma unroll
        for (int kk = 0; kk < 4; kk++) {
            uint32_t af[4][4];
            #pragma unroll
            for (int ma = 0; ma < 4; ma++)
                ldsm_x4(af[ma], smem_u32(&As[s][ma * 16 + a_m][kk * 8 + a_k]));
            uint32_t bf[4][2];
            #pragma unroll
            for (int na = 0; na < 4; na++) {
                bf[na][0] = f2tf32(Bs[s][kk * 8 + t    ][wid * 32 + na * 8 + g]);
                bf[na][1] = f2tf32(Bs[s][kk * 8 + t + 4][wid * 32 + na * 8 + g]);
            }
            #pragma unroll
            for (int ma = 0; ma < 4; ma++)
                #pragma unroll
                for (int na = 0; na < 4; na++)
                    mma_tf32(acc[ma][na], af[ma], bf[na]);
        }
        if (i + 1 < nchunk) asm volatile("cp.async.wait_group 0;" ::: "memory");
        __syncthreads();
    }
    #pragma unroll
    for (int ma = 0; ma < 4; ma++) {
        #pragma unroll
        for (int na = 0; na < 4; na++) {
            const int row = bm + ma * 16 + g;
            const int col = bn + wid * 32 + na * 8 + (t << 1);
            *(float2*)&Cb[(size_t)row * N + col]       = make_float2(acc[ma][na][0], acc[ma][na][1]);
            *(float2*)&Cb[(size_t)(row + 8) * N + col] = make_float2(acc[ma][na][2], acc[ma][na][3]);
        }
    }
}

// ---------------- zero S + convert qk-weights to bf16 + v-weights to tf32 ----------------
__global__ void k_zero(const float* __restrict__ w_qkv) {
    int i = blockIdx.x * blockDim.x + threadIdx.x;
    if (i < BATCH*HEADS*CHD*CHD) g_S[i] = 0.f;
    if (i < 384*CDIM) g_wqkb[i] = __float2bfloat16(w_qkv[i]);
    if (i < CDIM*CDIM) g_wvt[i] = __uint_as_float(f2tf32(w_qkv[384*CDIM + i]));
}

// =============== rolling-window f32x2 depthwise 3x3 core pieces ===============
__device__ __forceinline__ void conv_loadP(const float* s, int sr, int x4, int lane, ull* P) {
    const float* rp = &s[sr * 132 + x4];
    float4 q = *(const float4*)rp;
    float rx = rp[4];
    float lf = __shfl_up_sync(0xffffffffu, q.w, 1);
    if (lane == 0) lf = 0.f;
    P[0] = pack2(lf,  q.x);
    P[1] = pack2(q.x, q.y);
    P[2] = pack2(q.y, q.z);
    P[3] = pack2(q.z, q.w);
    P[4] = pack2(q.w, rx);
}

#define CONV_ACC(a01, a23, P, o, Wp)                                        \
    {                                                                        \
        _Pragma("unroll")                                                    \
        for (int r = 0; r < 3; r++) {                                        \
            const ull* Q = P[((o) + r) % 3];                                 \
            ffma2(a01, Q[0], Wp[3*r+0]); ffma2(a01, Q[1], Wp[3*r+1]);        \
            ffma2(a01, Q[2], Wp[3*r+2]);                                     \
            ffma2(a23, Q[2], Wp[3*r+0]); ffma2(a23, Q[3], Wp[3*r+1]);        \
            ffma2(a23, Q[4], Wp[3*r+2]);                                     \
        }                                                                    \
    }

// ---------------- depthwise 3x3 on x + variance + x->bf16 emit ----------------
__global__ __launch_bounds__(256) void k_dw_var(const float* __restrict__ x,
                                                const float* __restrict__ wdw)
{
    __shared__ float s[66*132];
    __shared__ float red[64];
    const int bc = blockIdx.x;
    const float* plane = x + (size_t)bc * HW;
    __nv_bfloat16* xbp = g_xb + (size_t)bc * HW;
    const int c = bc % CDIM;
    const int tid = threadIdx.x;
    const int lane = tid & 31;
    const int strip = tid >> 5;
    const int x4 = lane << 2;
    ull Wp[9];
    #pragma unroll
    for (int i = 0; i < 9; i++) { float w = wdw[c*9 + i]; Wp[i] = pack2(w, w); }
    ull accS = 0ull, accQ = 0ull;

    for (int half = 0; half < 2; half++) {
        if (half) __syncthreads();
        const int y0 = half * 64;
        for (int i = tid; i < 66*32; i += 256) {
            int r = i >> 5, j4 = (i & 31) << 2;
            int y = y0 + r - 1;
            float4 v = make_float4(0.f, 0.f, 0.f, 0.f);
            if ((unsigned)y < 128u) v = *(const float4*)&plane[y*128 + j4];
            *(float4*)&s[r*132 + j4] = v;
            if (r >= 1 && r <= 64 && (unsigned)y < 128u) {
                __nv_bfloat162 h0 = __floats2bfloat162_rn(v.x, v.y);
                __nv_bfloat162 h1 = __floats2bfloat162_rn(v.z, v.w);
                uint2 u; u.x = *(uint32_t*)&h0; u.y = *(uint32_t*)&h1;
                *(uint2*)&xbp[y*128 + j4] = u;
            }
        }
        for (int i = tid; i < 66; i += 256) { s[i*132+128] = 0.f; s[i*132+129] = 0.f; }
        __syncthreads();

        ull P[3][5];
        const int base = strip * 8;
        conv_loadP(s, base,     x4, lane, P[0]);
        conv_loadP(s, base + 1, x4, lane, P[1]);
        #pragma unroll
        for (int o = 0; o < 8; o++) {
            conv_loadP(s, base + o + 2, x4, lane, P[(o + 2) % 3]);
            ull a01 = 0ull, a23 = 0ull;
            CONV_ACC(a01, a23, P, o, Wp);
            add2(accS, a01); add2(accS, a23);
            ffma2(accQ, a01, a01); ffma2(accQ, a23, a23);
        }
    }
    float2 S2 = unpack2(accS), Q2 = unpack2(accQ);
    float sum = S2.x + S2.y, sq = Q2.x + Q2.y;
    #pragma unroll
    for (int o = 16; o > 0; o >>= 1) {
        sum += __shfl_down_sync(0xffffffffu, sum, o);
        sq  += __shfl_down_sync(0xffffffffu, sq,  o);
    }
    if (lane == 0) { red[strip] = sum; red[32 + strip] = sq; }
    __syncthreads();
    if (tid == 0) {
        float S = 0.f, Q = 0.f;
        #pragma unroll
        for (int i = 0; i < 8; i++) { S += red[i]; Q += red[32+i]; }
        g_var[bc] = (Q - S*S*(1.f/16384.f)) * (1.f/16383.f);
    }
}

// ---------------- depthwise 3x3 on qkv: q,k bf16->bf16 (+norms), v fp32->fp32 ----------------
__global__ __launch_bounds__(256) void k_dw_qkv(const float* __restrict__ wdw)
{
    __shared__ float s[66*132];
    __shared__ float red[8];
    const int bc = blockIdx.x;
    const int ch = bc % C3;
    const int b  = bc / C3;
    const bool is_qk = ch < 384;
    const __nv_bfloat16* planeb = g_qkb + ((size_t)b*384 + ch) * HW;
    const float*         planef = g_vpre + ((size_t)b*CDIM + (ch - 384)) * HW;
    __nv_bfloat16* outb = g_qk + ((size_t)b*384 + ch) * HW;
    float*         outv = g_v  + ((size_t)b*CDIM + (ch - 384)) * HW;
    const int tid = threadIdx.x;
    const int lane = tid & 31;
    const int strip = tid >> 5;
    const int x4 = lane << 2;
    ull Wp[9];
    #pragma unroll
    for (int i = 0; i < 9; i++) { float w = wdw[ch*9 + i]; Wp[i] = pack2(w, w); }
    float sq = 0.f;

    for (int half = 0; half < 2; half++) {
        if (half) __syncthreads();
        const int y0 = half * 64;
        if (is_qk) {
            for (int i = tid; i < 66*32; i += 256) {
                int r = i >> 5, j4 = (i & 31) << 2;
                int y = y0 + r - 1;
                float4 v = make_float4(0.f, 0.f, 0.f, 0.f);
                if ((unsigned)y < 128u) {
                    uint2 u = *(const uint2*)&planeb[y*128 + j4];
                    float2 f0 = __bfloat1622float2(*(__nv_bfloat162*)&u.x);
                    float2 f1 = __bfloat1622float2(*(__nv_bfloat162*)&u.y);
                    v = make_float4(f0.x, f0.y, f1.x, f1.y);
                }
                *(float4*)&s[r*132 + j4] = v;
            }
        } else {
            for (int i = tid; i < 66*32; i += 256) {
                int r = i >> 5, j4 = (i & 31) << 2;
                int y = y0 + r - 1;
                float4 v = make_float4(0.f, 0.f, 0.f, 0.f);
                if ((unsigned)y < 128u) v = *(const float4*)&planef[y*128 + j4];
                *(float4*)&s[r*132 + j4] = v;
            }
        }
        for (int i = tid; i < 66; i += 256) { s[i*132+128] = 0.f; s[i*132+129] = 0.f; }
        __syncthreads();

        ull P[3][5];
        const int base = strip * 8;
        conv_loadP(s, base,     x4, lane, P[0]);
        conv_loadP(s, base + 1, x4, lane, P[1]);
        #pragma unroll
        for (int o = 0; o < 8; o++) {
            conv_loadP(s, base + o + 2, x4, lane, P[(o + 2) % 3]);
            ull a01 = 0ull, a23 = 0ull;
            CONV_ACC(a01, a23, P, o, Wp);
            const int y = y0 + base + o;
            float2 v01 = unpack2(a01), v23 = unpack2(a23);
            if (is_qk) {
                __nv_bfloat162 h0 = __floats2bfloat162_rn(v01.x, v01.y);
                __nv_bfloat162 h1 = __floats2bfloat162_rn(v23.x, v23.y);
                uint2 st;
                st.x = *(uint32_t*)&h0; st.y = *(uint32_t*)&h1;
                *(uint2*)&outb[y*128 + x4] = st;
                float2 r0 = __bfloat1622float2(h0), r1 = __bfloat1622float2(h1);
                sq += r0.x*r0.x + r0.y*r0.y + r1.x*r1.x + r1.y*r1.y;
            } else {
                *(float4*)&outv[y*128 + x4] = make_float4(v01.x, v01.y, v23.x, v23.y);
            }
        }
    }
    if (is_qk) {
        #pragma unroll
        for (int o = 16; o > 0; o >>= 1) sq += __shfl_down_sync(0xffffffffu, sq, o);
        if (lane == 0) red[strip] = sq;
        __syncthreads();
        if (tid == 0) {
            float Q = 0.f;
            #pragma unroll
            for (int i = 0; i < 8; i++) Q += red[i];
            g_norm[b*384 + ch] = Q;
        }
    }
}

// ---------------- S = q @ k^T per (b,h) from bf16, split-K with atomics ----------------
__global__ __launch_bounds__(144) void k_qk()
{
    __shared__ float qs[24][64];
    __shared__ float ks[24][64];
    const int bh = blockIdx.x;
    const int b = bh >> 3, h = bh & 7;
    const __nv_bfloat16* qb = g_qk + ((size_t)b*384 + h*CHD) * HW;
    const __nv_bfloat16* kb = g_qk + ((size_t)b*384 + 192 + h*CHD) * HW;
    const int n0 = blockIdx.y * 1024;
    const int tid = threadIdx.x;
    const int sub = tid & 3;
    const int cd  = tid >> 2;
    const int c0 = (cd / 6) * 4, d0 = (cd % 6) * 4;
    float acc[4][4] = {};
    for (int chk = 0; chk < 16; chk++) {
        if (chk) __syncthreads();
        const int nn = n0 + chk * 64;
        for (int i = tid; i < 24*32; i += 144) {
            int r = i >> 5, j2 = (i & 31) << 1;
            __nv_bfloat162 q2 = *(const __nv_bfloat162*)&qb[(size_t)r*HW + nn + j2];
            __nv_bfloat162 k2 = *(const __nv_bfloat162*)&kb[(size_t)r*HW + nn + j2];
            *(float2*)&qs[r][j2] = __bfloat1622float2(q2);
            *(float2*)&ks[r][j2] = __bfloat1622float2(k2);
        }
        __syncthreads();
        const int j0 = sub * 16;
        #pragma unroll 4
        for (int j = j0; j < j0 + 16; j++) {
            float q0 = qs[c0+0][j], q1 = qs[c0+1][j], q2 = qs[c0+2][j], q3 = qs[c0+3][j];
            float k0 = ks[d0+0][j], k1 = ks[d0+1][j], k2 = ks[d0+2][j], k3 = ks[d0+3][j];
            acc[0][0] += q0*k0; acc[0][1] += q0*k1; acc[0][2] += q0*k2; acc[0][3] += q0*k3;
            acc[1][0] += q1*k0; acc[1][1] += q1*k1; acc[1][2] += q1*k2; acc[1][3] += q1*k3;
            acc[2][0] += q2*k0; acc[2][1] += q2*k1; acc[2][2] += q2*k2; acc[2][3] += q2*k3;
            acc[3][0] += q3*k0; acc[3][1] += q3*k1; acc[3][2] += q3*k2; acc[3][3] += q3*k3;
        }
    }
    #pragma unroll
    for (int i = 0; i < 4; i++)
        #pragma unroll
        for (int l = 0; l < 4; l++)
            atomicAdd(&g_S[(size_t)bh*576 + (c0+i)*24 + (d0+l)], acc[i][l]);
}

// ---------------- softmax + M = Wproj @ blockdiag(attn), M emitted tf32-formatted ----------------
__global__ __launch_bounds__(192) void k_soft(const float* __restrict__ temp,
                                              const float* __restrict__ resc,
                                              const float* __restrict__ wproj)
{
    __shared__ float a[24][24];
    const int h = blockIdx.x, b = blockIdx.y;
    const int tid = threadIdx.x;
    const float* Sp = g_S + (size_t)(b*8 + h) * 576;
    const float t = temp[h];
    for (int idx = tid; idx < 576; idx += 192) {
        int c = idx / 24, d = idx % 24;
        float nq = sqrtf(g_norm[b*384 + h*24 + c]);
        float nk = sqrtf(g_norm[b*384 + 192 + h*24 + d]);
        float denom = fmaxf(nq, 1e-12f) * fmaxf(nk, 1e-12f);
        float l = Sp[idx] / denom * t;
        if (c == d) l += resc[h] * g_var[b*192 + h*24 + c];
        a[c][d] = l;
    }
    __syncthreads();
    if (tid < 24) {
        const int c = tid;
        float m = -1e30f;
        #pragma unroll
        for (int d = 0; d < 24; d++) m = fmaxf(m, a[c][d]);
        float e[24]; float ssum = 0.f;
        #pragma unroll
        for (int d = 0; d < 24; d++) { e[d] = expf(a[c][d] - m); ssum += e[d]; }
        float inv = 1.f / ssum;
        #pragma unroll
        for (int d = 0; d < 24; d++) a[c][d] = e[d] * inv;
    }
    __syncthreads();
    const int co = tid;
    float wr[24];
    #pragma unroll
    for (int c = 0; c < 24; c++) wr[c] = wproj[(size_t)co*CDIM + h*24 + c];
    float* Mp = g_M + (size_t)b*CDIM*CDIM + (size_t)co*CDIM + h*24;
    #pragma unroll 4
    for (int d = 0; d < 24; d++) {
        float accv = 0.f;
        #pragma unroll
        for (int c = 0; c < 24; c++) accv += wr[c] * a[c][d];
        Mp[d] = __uint_as_float(f2tf32(accv));   // pre-converted for gemm2 A-side
    }
}

// ---------------- launch ----------------
extern "C" void kernel_launch(void* const* d_in, const int* in_sizes, int n_in,
                              void* d_out, int out_size)
{
    const float* x       = (const float*)d_in[0];
    const float* w_dw    = (const float*)d_in[1];
    const float* w_qkv   = (const float*)d_in[2];
    const float* w_qkvdw = (const float*)d_in[3];
    const float* w_proj  = (const float*)d_in[4];
    const float* temp    = (const float*)d_in[5];
    const float* resc    = (const float*)d_in[6];
    float* out = (float*)d_out;

    float *vprep, *vp, *Mp, *wvtp;
    __nv_bfloat16 *qkbp, *xbp, *wqkbp;
    cudaGetSymbolAddress((void**)&qkbp,  g_qkb);
    cudaGetSymbolAddress((void**)&xbp,   g_xb);
    cudaGetSymbolAddress((void**)&wqkbp, g_wqkb);
    cudaGetSymbolAddress((void**)&wvtp,  g_wvt);
    cudaGetSymbolAddress((void**)&vprep, g_vpre);
    cudaGetSymbolAddress((void**)&vp,    g_v);
    cudaGetSymbolAddress((void**)&Mp,    g_M);

    cudaFuncSetAttribute(gemm_mma,  cudaFuncAttributePreferredSharedMemoryCarveout, 90);
    cudaFuncSetAttribute(gemm_bf16, cudaFuncAttributePreferredSharedMemoryCarveout, 90);

    k_zero<<<72, 1024>>>(w_qkv);
    k_dw_var<<<BATCH*CDIM, 256>>>(x, w_dw);     // also emits g_xb (bf16 x)
    // q,k rows of 1x1 conv (bf16 tensor path): [384,HW] = Wqk[384,192] @ xb[192,HW]
    gemm_bf16<<<dim3(6, 64, BATCH), 256>>>(wqkbp, xbp, qkbp);
    // v rows (tf32 path, A pre-converted): [192,HW] = Wv_t32[192,192] @ x[192,HW]
    gemm_mma<<<dim3(3, 64, BATCH), 256>>>(wvtp, x, vprep,
        CDIM, HW, CDIM, 0LL, (long long)CDIM*HW, (long long)CDIM*HW);
    k_dw_qkv<<<BATCH*C3, 256>>>(w_qkvdw);
    k_qk<<<dim3(64, 16), 144>>>();
    k_soft<<<dim3(HEADS, BATCH), 192>>>(temp, resc, w_proj);
    // final: out[b] = M_t32[b](192x192) @ V[b](192,HW)
    gemm_mma<<<dim3(3, 64, BATCH), 256>>>(Mp, vp, out,
        CDIM, HW, CDIM, (long long)CDIM*CDIM, (long long)CDIM*HW, (long long)CDIM*HW);
}

// round 13
// speedup vs baseline: 1.0100x; 1.0100x over previous
#include <cuda_runtime.h>
#include <cuda_bf16.h>
#include <cstdint>

#define HW   16384
#define CDIM 192
#define C3   576
#define BATCH 8
#define HEADS 8
#define CHD  24

typedef unsigned long long ull;

// ---------------- scratch (device globals: allocation-free rule) ----------------
__device__ __nv_bfloat16 g_xb [25165824];   // [8,192,16384] x in bf16 (for qk gemm)
__device__ __nv_bfloat16 g_wqkb[73728];     // [384,192] W_qkv rows 0..383 in bf16
__device__ float g_wvt [36864];             // [192,192] W_qkv v-rows, tf32-formatted
__device__ __nv_bfloat16 g_qkb[50331648];   // [8,384,16384] pre-conv q,k (bf16)
__device__ float g_vpre[25165824];          // [8,192,16384] pre-conv v (fp32)
__device__ __nv_bfloat16 g_qk[50331648];    // [8,384,16384] post-conv q,k (bf16)
__device__ float g_v  [25165824];           // [8,192,16384] post-conv v (fp32)
__device__ float g_var [BATCH*CDIM];
__device__ float g_norm[BATCH*384];
__device__ float g_S   [BATCH*HEADS*CHD*CHD];
__device__ float g_M   [BATCH*CDIM*CDIM];   // tf32-formatted by k_soft

__device__ __forceinline__ uint32_t smem_u32(const void* p) {
    uint32_t a;
    asm("{ .reg .u64 t; cvta.to.shared.u64 t, %1; cvt.u32.u64 %0, t; }" : "=r"(a) : "l"(p));
    return a;
}
__device__ __forceinline__ uint32_t f2tf32(float f) {
    uint32_t o;
    asm("cvt.rna.tf32.f32 %0, %1;" : "=r"(o) : "f"(f));
    return o;
}
__device__ __forceinline__ void mma_tf32(float* c, const uint32_t* a, const uint32_t* b) {
    asm("mma.sync.aligned.m16n8k8.row.col.f32.tf32.tf32.f32 "
        "{%0,%1,%2,%3}, {%4,%5,%6,%7}, {%8,%9}, {%0,%1,%2,%3};"
        : "+f"(c[0]), "+f"(c[1]), "+f"(c[2]), "+f"(c[3])
        : "r"(a[0]), "r"(a[1]), "r"(a[2]), "r"(a[3]), "r"(b[0]), "r"(b[1]));
}
__device__ __forceinline__ void mma_bf16(float* c, const uint32_t* a, const uint32_t* b) {
    asm("mma.sync.aligned.m16n8k16.row.col.f32.bf16.bf16.f32 "
        "{%0,%1,%2,%3}, {%4,%5,%6,%7}, {%8,%9}, {%0,%1,%2,%3};"
        : "+f"(c[0]), "+f"(c[1]), "+f"(c[2]), "+f"(c[3])
        : "r"(a[0]), "r"(a[1]), "r"(a[2]), "r"(a[3]), "r"(b[0]), "r"(b[1]));
}
__device__ __forceinline__ void ldsm_x4(uint32_t* r, uint32_t addr) {
    asm("ldmatrix.sync.aligned.m8n8.x4.shared.b16 {%0,%1,%2,%3}, [%4];"
        : "=r"(r[0]), "=r"(r[1]), "=r"(r[2]), "=r"(r[3]) : "r"(addr));
}
__device__ __forceinline__ void ldsm_x4t(uint32_t* r, uint32_t addr) {
    asm("ldmatrix.sync.aligned.m8n8.x4.trans.shared.b16 {%0,%1,%2,%3}, [%4];"
        : "=r"(r[0]), "=r"(r[1]), "=r"(r[2]), "=r"(r[3]) : "r"(addr));
}
__device__ __forceinline__ void cp_async16(uint32_t dst, const void* src) {
    asm volatile("cp.async.cg.shared.global [%0], [%1], 16;" :: "r"(dst), "l"(src) : "memory");
}
__device__ __forceinline__ ull pack2(float a, float b) {
    ull r; asm("mov.b64 %0, {%1,%2};" : "=l"(r) : "f"(a), "f"(b)); return r;
}
__device__ __forceinline__ void ffma2(ull& acc, ull a, ull b) {
    asm("fma.rn.f32x2 %0, %1, %2, %0;" : "+l"(acc) : "l"(a), "l"(b));
}
__device__ __forceinline__ void add2(ull& acc, ull a) {
    asm("add.rn.f32x2 %0, %0, %1;" : "+l"(acc) : "l"(a));
}
__device__ __forceinline__ float2 unpack2(ull v) {
    float2 o; asm("mov.b64 {%0,%1}, %2;" : "=f"(o.x), "=f"(o.y) : "l"(v)); return o;
}

// ================= bf16 mma GEMM for q,k rows: C[384,HW] = A[384,192] @ B[192,HW] =================
// BM=64, BN=256, BK=32, *** 3-stage cp.async pipeline (wait_group 1) ***, 256 threads.
// Stage smem = As 5KB + Bs 16.5KB; 3 stages = 64.7KB/block -> still 2 blocks/SM.
__global__ void __launch_bounds__(256, 2) gemm_bf16(
    const __nv_bfloat16* __restrict__ A,
    const __nv_bfloat16* __restrict__ B,
    __nv_bfloat16* __restrict__ C)
{
    __shared__ __nv_bfloat16 As[3][64][40];
    __shared__ __nv_bfloat16 Bs[3][32][264];
    const int tid = threadIdx.x, lane = tid & 31, wid = tid >> 5;
    const int g = lane >> 2, t = lane & 3;
    const int bm = blockIdx.x * 64, bn = blockIdx.y * 256;
    const __nv_bfloat16* Bb = B + (size_t)blockIdx.z * CDIM * HW;
    __nv_bfloat16* Cb = C + (size_t)blockIdx.z * 384 * HW;

    const int arow = tid >> 2, akc = (tid & 3) * 8;

    float acc[4][4][4];
    #pragma unroll
    for (int i = 0; i < 4; i++)
        #pragma unroll
        for (int j = 0; j < 4; j++)
            #pragma unroll
            for (int l = 0; l < 4; l++) acc[i][j][l] = 0.f;

    const int a_m = (lane & 15);
    const int a_k = ((lane >> 4) & 1) * 8;
    const int b_k = (lane & 7) + ((lane >> 3) & 1) * 8;
    const int b_n = wid * 32 + ((lane >> 4) & 1) * 8;

    // ---- preload stages 0 and 1 (one commit group each) ----
    #pragma unroll
    for (int st = 0; st < 2; st++) {
        const int k0 = st * 32;
        cp_async16(smem_u32(&As[st][arow][akc]), &A[(size_t)(bm + arow) * 192 + k0 + akc]);
        #pragma unroll
        for (int p = 0; p < 4; p++) {
            int c = tid + p * 256;
            int kr = c >> 5, nc = (c & 31) * 8;
            cp_async16(smem_u32(&Bs[st][kr][nc]), &Bb[(size_t)(k0 + kr) * HW + bn + nc]);
        }
        asm volatile("cp.async.commit_group;" ::: "memory");
    }

    #pragma unroll 1
    for (int i = 0; i < 6; i++) {
        const int s = i % 3;
        // stage i's group complete; stage i+1's group may remain in flight
        if (i < 4) asm volatile("cp.async.wait_group 1;" ::: "memory");
        else       asm volatile("cp.async.wait_group 0;" ::: "memory");
        __syncthreads();   // all warps done consuming stage (i+2)%3 (used at iter i-1)
        if (i + 2 < 6) {
            const int sn = (i + 2) % 3;
            const int k0 = (i + 2) * 32;
            cp_async16(smem_u32(&As[sn][arow][akc]), &A[(size_t)(bm + arow) * 192 + k0 + akc]);
            #pragma unroll
            for (int p = 0; p < 4; p++) {
                int c = tid + p * 256;
                int kr = c >> 5, nc = (c & 31) * 8;
                cp_async16(smem_u32(&Bs[sn][kr][nc]), &Bb[(size_t)(k0 + kr) * HW + bn + nc]);
            }
            asm volatile("cp.async.commit_group;" ::: "memory");
        }
        #pragma unroll
        for (int kk = 0; kk < 2; kk++) {
            uint32_t af[4][4];
            #pragma unroll
            for (int ma = 0; ma < 4; ma++)
                ldsm_x4(af[ma], smem_u32(&As[s][ma * 16 + a_m][kk * 16 + a_k]));
            uint32_t bf[4][4];
            #pragma unroll
            for (int p = 0; p < 2; p++)
                ldsm_x4t(bf[p], smem_u32(&Bs[s][kk * 16 + b_k][b_n + p * 16]));
            #pragma unroll
            for (int ma = 0; ma < 4; ma++) {
                #pragma unroll
                for (int p = 0; p < 2; p++) {
                    mma_bf16(acc[ma][p * 2 + 0], af[ma], &bf[p][0]);
                    mma_bf16(acc[ma][p * 2 + 1], af[ma], &bf[p][2]);
                }
            }
        }
    }
    #pragma unroll
    for (int ma = 0; ma < 4; ma++) {
        #pragma unroll
        for (int nt = 0; nt < 4; nt++) {
            const int row = bm + ma * 16 + g;
            const int col = bn + wid * 32 + (nt >> 1) * 16 + (nt & 1) * 8 + 2 * t;
            __nv_bfloat162 h0 = __floats2bfloat162_rn(acc[ma][nt][0], acc[ma][nt][1]);
            __nv_bfloat162 h1 = __floats2bfloat162_rn(acc[ma][nt][2], acc[ma][nt][3]);
            *(__nv_bfloat162*)&Cb[(size_t)row * HW + col]       = h0;
            *(__nv_bfloat162*)&Cb[(size_t)(row + 8) * HW + col] = h1;
        }
    }
}

// ================= tf32 mma.sync GEMM, BN=256, BK=32, A pre-converted to tf32 =================
__global__ void __launch_bounds__(256, 2) gemm_mma(
    const float* __restrict__ A, const float* __restrict__ B, float* __restrict__ C,
    int M, int N, int K, long long sA, long long sB, long long sC)
{
    __shared__ float As[2][64][36];
    __shared__ float Bs[2][32][264];
    const int tid  = threadIdx.x;
    const int lane = tid & 31;
    const int wid  = tid >> 5;
    const int g    = lane >> 2;
    const int t    = lane & 3;
    const float* Ab = A + (long long)blockIdx.z * sA;
    const float* Bb = B + (long long)blockIdx.z * sB;
    float*       Cb = C + (long long)blockIdx.z * sC;
    const int bm = blockIdx.x * 64;
    const int bn = blockIdx.y * 256;

    const int arow = tid >> 2;            // 0..63
    const int acol = (tid & 3) * 8;       // 0,8,16,24
    const int a_m = lane & 15;
    const int a_k = (lane >> 4) * 4;

    float acc[4][4][4];
    #pragma unroll
    for (int i = 0; i < 4; i++)
        #pragma unroll
        for (int j = 0; j < 4; j++)
            #pragma unroll
            for (int l = 0; l < 4; l++) acc[i][j][l] = 0.f;

    // ---- preload stage 0 (all cp.async) ----
    cp_async16(smem_u32(&As[0][arow][acol]),     &Ab[(size_t)(bm + arow) * K + acol]);
    cp_async16(smem_u32(&As[0][arow][acol + 4]), &Ab[(size_t)(bm + arow) * K + acol + 4]);
    #pragma unroll
    for (int p = 0; p < 8; p++) {
        int c = tid + p * 256;
        int kr = c >> 6, nc = (c & 63) * 4;
        cp_async16(smem_u32(&Bs[0][kr][nc]), &Bb[(size_t)kr * N + bn + nc]);
    }
    asm volatile("cp.async.commit_group;" ::: "memory");
    asm volatile("cp.async.wait_group 0;" ::: "memory");
    __syncthreads();

    const int nchunk = K >> 5;    // 6 for K=192
    #pragma unroll 1
    for (int i = 0; i < nchunk; i++) {
        const int s = i & 1;
        if (i + 1 < nchunk) {
            const int k0 = (i + 1) << 5;
            cp_async16(smem_u32(&As[s ^ 1][arow][acol]),     &Ab[(size_t)(bm + arow) * K + k0 + acol]);
            cp_async16(smem_u32(&As[s ^ 1][arow][acol + 4]), &Ab[(size_t)(bm + arow) * K + k0 + acol + 4]);
            #pragma unroll
            for (int p = 0; p < 8; p++) {
                int c = tid + p * 256;
                int kr = c >> 6, nc = (c & 63) * 4;
                cp_async16(smem_u32(&Bs[s ^ 1][kr][nc]), &Bb[(size_t)(k0 + kr) * N + bn + nc]);
            }
            asm volatile("cp.async.commit_group;" ::: "memory");
        }
        #pragma unroll
        for (int kk = 0; kk < 4; kk++) {
            uint32_t af[4][4];
            #pragma unroll
            for (int ma = 0; ma < 4; ma++)
                ldsm_x4(af[ma], smem_u32(&As[s][ma * 16 + a_m][kk * 8 + a_k]));
            uint32_t bf[4][2];
            #pragma unroll
            for (int na = 0; na < 4; na++) {
                bf[na][0] = f2tf32(Bs[s][kk * 8 + t    ][wid * 32 + na * 8 + g]);
                bf[na][1] = f2tf32(Bs[s][kk * 8 + t + 4][wid * 32 + na * 8 + g]);
            }
            #pragma unroll
            for (int ma = 0; ma < 4; ma++)
                #pragma unroll
                for (int na = 0; na < 4; na++)
                    mma_tf32(acc[ma][na], af[ma], bf[na]);
        }
        if (i + 1 < nchunk) asm volatile("cp.async.wait_group 0;" ::: "memory");
        __syncthreads();
    }
    #pragma unroll
    for (int ma = 0; ma < 4; ma++) {
        #pragma unroll
        for (int na = 0; na < 4; na++) {
            const int row = bm + ma * 16 + g;
            const int col = bn + wid * 32 + na * 8 + (t << 1);
            *(float2*)&Cb[(size_t)row * N + col]       = make_float2(acc[ma][na][0], acc[ma][na][1]);
            *(float2*)&Cb[(size_t)(row + 8) * N + col] = make_float2(acc[ma][na][2], acc[ma][na][3]);
        }
    }
}

// ---------------- zero S + convert qk-weights to bf16 + v-weights to tf32 ----------------
__global__ void k_zero(const float* __restrict__ w_qkv) {
    int i = blockIdx.x * blockDim.x + threadIdx.x;
    if (i < BATCH*HEADS*CHD*CHD) g_S[i] = 0.f;
    if (i < 384*CDIM) g_wqkb[i] = __float2bfloat16(w_qkv[i]);
    if (i < CDIM*CDIM) g_wvt[i] = __uint_as_float(f2tf32(w_qkv[384*CDIM + i]));
}

// =============== rolling-window f32x2 depthwise 3x3 core pieces ===============
__device__ __forceinline__ void conv_loadP(const float* s, int sr, int x4, int lane, ull* P) {
    const float* rp = &s[sr * 132 + x4];
    float4 q = *(const float4*)rp;
    float rx = rp[4];
    float lf = __shfl_up_sync(0xffffffffu, q.w, 1);
    if (lane == 0) lf = 0.f;
    P[0] = pack2(lf,  q.x);
    P[1] = pack2(q.x, q.y);
    P[2] = pack2(q.y, q.z);
    P[3] = pack2(q.z, q.w);
    P[4] = pack2(q.w, rx);
}

#define CONV_ACC(a01, a23, P, o, Wp)                                        \
    {                                                                        \
        _Pragma("unroll")                                                    \
        for (int r = 0; r < 3; r++) {                                        \
            const ull* Q = P[((o) + r) % 3];                                 \
            ffma2(a01, Q[0], Wp[3*r+0]); ffma2(a01, Q[1], Wp[3*r+1]);        \
            ffma2(a01, Q[2], Wp[3*r+2]);                                     \
            ffma2(a23, Q[2], Wp[3*r+0]); ffma2(a23, Q[3], Wp[3*r+1]);        \
            ffma2(a23, Q[4], Wp[3*r+2]);                                     \
        }                                                                    \
    }

// ---------------- depthwise 3x3 on x + variance + x->bf16 emit ----------------
__global__ __launch_bounds__(256) void k_dw_var(const float* __restrict__ x,
                                                const float* __restrict__ wdw)
{
    __shared__ float s[66*132];
    __shared__ float red[64];
    const int bc = blockIdx.x;
    const float* plane = x + (size_t)bc * HW;
    __nv_bfloat16* xbp = g_xb + (size_t)bc * HW;
    const int c = bc % CDIM;
    const int tid = threadIdx.x;
    const int lane = tid & 31;
    const int strip = tid >> 5;
    const int x4 = lane << 2;
    ull Wp[9];
    #pragma unroll
    for (int i = 0; i < 9; i++) { float w = wdw[c*9 + i]; Wp[i] = pack2(w, w); }
    ull accS = 0ull, accQ = 0ull;

    for (int half = 0; half < 2; half++) {
        if (half) __syncthreads();
        const int y0 = half * 64;
        for (int i = tid; i < 66*32; i += 256) {
            int r = i >> 5, j4 = (i & 31) << 2;
            int y = y0 + r - 1;
            float4 v = make_float4(0.f, 0.f, 0.f, 0.f);
            if ((unsigned)y < 128u) v = *(const float4*)&plane[y*128 + j4];
            *(float4*)&s[r*132 + j4] = v;
            if (r >= 1 && r <= 64 && (unsigned)y < 128u) {
                __nv_bfloat162 h0 = __floats2bfloat162_rn(v.x, v.y);
                __nv_bfloat162 h1 = __floats2bfloat162_rn(v.z, v.w);
                uint2 u; u.x = *(uint32_t*)&h0; u.y = *(uint32_t*)&h1;
                *(uint2*)&xbp[y*128 + j4] = u;
            }
        }
        for (int i = tid; i < 66; i += 256) { s[i*132+128] = 0.f; s[i*132+129] = 0.f; }
        __syncthreads();

        ull P[3][5];
        const int base = strip * 8;
        conv_loadP(s, base,     x4, lane, P[0]);
        conv_loadP(s, base + 1, x4, lane, P[1]);
        #pragma unroll
        for (int o = 0; o < 8; o++) {
            conv_loadP(s, base + o + 2, x4, lane, P[(o + 2) % 3]);
            ull a01 = 0ull, a23 = 0ull;
            CONV_ACC(a01, a23, P, o, Wp);
            add2(accS, a01); add2(accS, a23);
            ffma2(accQ, a01, a01); ffma2(accQ, a23, a23);
        }
    }
    float2 S2 = unpack2(accS), Q2 = unpack2(accQ);
    float sum = S2.x + S2.y, sq = Q2.x + Q2.y;
    #pragma unroll
    for (int o = 16; o > 0; o >>= 1) {
        sum += __shfl_down_sync(0xffffffffu, sum, o);
        sq  += __shfl_down_sync(0xffffffffu, sq,  o);
    }
    if (lane == 0) { red[strip] = sum; red[32 + strip] = sq; }
    __syncthreads();
    if (tid == 0) {
        float S = 0.f, Q = 0.f;
        #pragma unroll
        for (int i = 0; i < 8; i++) { S += red[i]; Q += red[32+i]; }
        g_var[bc] = (Q - S*S*(1.f/16384.f)) * (1.f/16383.f);
    }
}

// ---------------- depthwise 3x3 on qkv: q,k bf16->bf16 (+norms), v fp32->fp32 ----------------
__global__ __launch_bounds__(256) void k_dw_qkv(const float* __restrict__ wdw)
{
    __shared__ float s[66*132];
    __shared__ float red[8];
    const int bc = blockIdx.x;
    const int ch = bc % C3;
    const int b  = bc / C3;
    const bool is_qk = ch < 384;
    const __nv_bfloat16* planeb = g_qkb + ((size_t)b*384 + ch) * HW;
    const float*         planef = g_vpre + ((size_t)b*CDIM + (ch - 384)) * HW;
    __nv_bfloat16* outb = g_qk + ((size_t)b*384 + ch) * HW;
    float*         outv = g_v  + ((size_t)b*CDIM + (ch - 384)) * HW;
    const int tid = threadIdx.x;
    const int lane = tid & 31;
    const int strip = tid >> 5;
    const int x4 = lane << 2;
    ull Wp[9];
    #pragma unroll
    for (int i = 0; i < 9; i++) { float w = wdw[ch*9 + i]; Wp[i] = pack2(w, w); }
    float sq = 0.f;

    for (int half = 0; half < 2; half++) {
        if (half) __syncthreads();
        const int y0 = half * 64;
        if (is_qk) {
            for (int i = tid; i < 66*32; i += 256) {
                int r = i >> 5, j4 = (i & 31) << 2;
                int y = y0 + r - 1;
                float4 v = make_float4(0.f, 0.f, 0.f, 0.f);
                if ((unsigned)y < 128u) {
                    uint2 u = *(const uint2*)&planeb[y*128 + j4];
                    float2 f0 = __bfloat1622float2(*(__nv_bfloat162*)&u.x);
                    float2 f1 = __bfloat1622float2(*(__nv_bfloat162*)&u.y);
                    v = make_float4(f0.x, f0.y, f1.x, f1.y);
                }
                *(float4*)&s[r*132 + j4] = v;
            }
        } else {
            for (int i = tid; i < 66*32; i += 256) {
                int r = i >> 5, j4 = (i & 31) << 2;
                int y = y0 + r - 1;
                float4 v = make_float4(0.f, 0.f, 0.f, 0.f);
                if ((unsigned)y < 128u) v = *(const float4*)&planef[y*128 + j4];
                *(float4*)&s[r*132 + j4] = v;
            }
        }
        for (int i = tid; i < 66; i += 256) { s[i*132+128] = 0.f; s[i*132+129] = 0.f; }
        __syncthreads();

        ull P[3][5];
        const int base = strip * 8;
        conv_loadP(s, base,     x4, lane, P[0]);
        conv_loadP(s, base + 1, x4, lane, P[1]);
        #pragma unroll
        for (int o = 0; o < 8; o++) {
            conv_loadP(s, base + o + 2, x4, lane, P[(o + 2) % 3]);
            ull a01 = 0ull, a23 = 0ull;
            CONV_ACC(a01, a23, P, o, Wp);
            const int y = y0 + base + o;
            float2 v01 = unpack2(a01), v23 = unpack2(a23);
            if (is_qk) {
                __nv_bfloat162 h0 = __floats2bfloat162_rn(v01.x, v01.y);
                __nv_bfloat162 h1 = __floats2bfloat162_rn(v23.x, v23.y);
                uint2 st;
                st.x = *(uint32_t*)&h0; st.y = *(uint32_t*)&h1;
                *(uint2*)&outb[y*128 + x4] = st;
                float2 r0 = __bfloat1622float2(h0), r1 = __bfloat1622float2(h1);
                sq += r0.x*r0.x + r0.y*r0.y + r1.x*r1.x + r1.y*r1.y;
            } else {
                *(float4*)&outv[y*128 + x4] = make_float4(v01.x, v01.y, v23.x, v23.y);
            }
        }
    }
    if (is_qk) {
        #pragma unroll
        for (int o = 16; o > 0; o >>= 1) sq += __shfl_down_sync(0xffffffffu, sq, o);
        if (lane == 0) red[strip] = sq;
        __syncthreads();
        if (tid == 0) {
            float Q = 0.f;
            #pragma unroll
            for (int i = 0; i < 8; i++) Q += red[i];
            g_norm[b*384 + ch] = Q;
        }
    }
}

// ---------------- S = q @ k^T per (b,h) from bf16, split-K with atomics ----------------
__global__ __launch_bounds__(144) void k_qk()
{
    __shared__ float qs[24][64];
    __shared__ float ks[24][64];
    const int bh = blockIdx.x;
    const int b = bh >> 3, h = bh & 7;
    const __nv_bfloat16* qb = g_qk + ((size_t)b*384 + h*CHD) * HW;
    const __nv_bfloat16* kb = g_qk + ((size_t)b*384 + 192 + h*CHD) * HW;
    const int n0 = blockIdx.y * 1024;
    const int tid = threadIdx.x;
    const int sub = tid & 3;
    const int cd  = tid >> 2;
    const int c0 = (cd / 6) * 4, d0 = (cd % 6) * 4;
    float acc[4][4] = {};
    for (int chk = 0; chk < 16; chk++) {
        if (chk) __syncthreads();
        const int nn = n0 + chk * 64;
        for (int i = tid; i < 24*32; i += 144) {
            int r = i >> 5, j2 = (i & 31) << 1;
            __nv_bfloat162 q2 = *(const __nv_bfloat162*)&qb[(size_t)r*HW + nn + j2];
            __nv_bfloat162 k2 = *(const __nv_bfloat162*)&kb[(size_t)r*HW + nn + j2];
            *(float2*)&qs[r][j2] = __bfloat1622float2(q2);
            *(float2*)&ks[r][j2] = __bfloat1622float2(k2);
        }
        __syncthreads();
        const int j0 = sub * 16;
        #pragma unroll 4
        for (int j = j0; j < j0 + 16; j++) {
            float q0 = qs[c0+0][j], q1 = qs[c0+1][j], q2 = qs[c0+2][j], q3 = qs[c0+3][j];
            float k0 = ks[d0+0][j], k1 = ks[d0+1][j], k2 = ks[d0+2][j], k3 = ks[d0+3][j];
            acc[0][0] += q0*k0; acc[0][1] += q0*k1; acc[0][2] += q0*k2; acc[0][3] += q0*k3;
            acc[1][0] += q1*k0; acc[1][1] += q1*k1; acc[1][2] += q1*k2; acc[1][3] += q1*k3;
            acc[2][0] += q2*k0; acc[2][1] += q2*k1; acc[2][2] += q2*k2; acc[2][3] += q2*k3;
            acc[3][0] += q3*k0; acc[3][1] += q3*k1; acc[3][2] += q3*k2; acc[3][3] += q3*k3;
        }
    }
    #pragma unroll
    for (int i = 0; i < 4; i++)
        #pragma unroll
        for (int l = 0; l < 4; l++)
            atomicAdd(&g_S[(size_t)bh*576 + (c0+i)*24 + (d0+l)], acc[i][l]);
}

// ---------------- softmax + M = Wproj @ blockdiag(attn), M emitted tf32-formatted ----------------
__global__ __launch_bounds__(192) void k_soft(const float* __restrict__ temp,
                                              const float* __restrict__ resc,
                                              const float* __restrict__ wproj)
{
    __shared__ float a[24][24];
    const int h = blockIdx.x, b = blockIdx.y;
    const int tid = threadIdx.x;
    const float* Sp = g_S + (size_t)(b*8 + h) * 576;
    const float t = temp[h];
    for (int idx = tid; idx < 576; idx += 192) {
        int c = idx / 24, d = idx % 24;
        float nq = sqrtf(g_norm[b*384 + h*24 + c]);
        float nk = sqrtf(g_norm[b*384 + 192 + h*24 + d]);
        float denom = fmaxf(nq, 1e-12f) * fmaxf(nk, 1e-12f);
        float l = Sp[idx] / denom * t;
        if (c == d) l += resc[h] * g_var[b*192 + h*24 + c];
        a[c][d] = l;
    }
    __syncthreads();
    if (tid < 24) {
        const int c = tid;
        float m = -1e30f;
        #pragma unroll
        for (int d = 0; d < 24; d++) m = fmaxf(m, a[c][d]);
        float e[24]; float ssum = 0.f;
        #pragma unroll
        for (int d = 0; d < 24; d++) { e[d] = expf(a[c][d] - m); ssum += e[d]; }
        float inv = 1.f / ssum;
        #pragma unroll
        for (int d = 0; d < 24; d++) a[c][d] = e[d] * inv;
    }
    __syncthreads();
    const int co = tid;
    float wr[24];
    #pragma unroll
    for (int c = 0; c < 24; c++) wr[c] = wproj[(size_t)co*CDIM + h*24 + c];
    float* Mp = g_M + (size_t)b*CDIM*CDIM + (size_t)co*CDIM + h*24;
    #pragma unroll 4
    for (int d = 0; d < 24; d++) {
        float accv = 0.f;
        #pragma unroll
        for (int c = 0; c < 24; c++) accv += wr[c] * a[c][d];
        Mp[d] = __uint_as_float(f2tf32(accv));   // pre-converted for gemm2 A-side
    }
}

// ---------------- launch ----------------
extern "C" void kernel_launch(void* const* d_in, const int* in_sizes, int n_in,
                              void* d_out, int out_size)
{
    const float* x       = (const float*)d_in[0];
    const float* w_dw    = (const float*)d_in[1];
    const float* w_qkv   = (const float*)d_in[2];
    const float* w_qkvdw = (const float*)d_in[3];
    const float* w_proj  = (const float*)d_in[4];
    const float* temp    = (const float*)d_in[5];
    const float* resc    = (const float*)d_in[6];
    float* out = (float*)d_out;

    float *vprep, *vp, *Mp, *wvtp;
    __nv_bfloat16 *qkbp, *xbp, *wqkbp;
    cudaGetSymbolAddress((void**)&qkbp,  g_qkb);
    cudaGetSymbolAddress((void**)&xbp,   g_xb);
    cudaGetSymbolAddress((void**)&wqkbp, g_wqkb);
    cudaGetSymbolAddress((void**)&wvtp,  g_wvt);
    cudaGetSymbolAddress((void**)&vprep, g_vpre);
    cudaGetSymbolAddress((void**)&vp,    g_v);
    cudaGetSymbolAddress((void**)&Mp,    g_M);

    cudaFuncSetAttribute(gemm_mma,  cudaFuncAttributePreferredSharedMemoryCarveout, 90);
    cudaFuncSetAttribute(gemm_bf16, cudaFuncAttributePreferredSharedMemoryCarveout, 90);

    k_zero<<<72, 1024>>>(w_qkv);
    k_dw_var<<<BATCH*CDIM, 256>>>(x, w_dw);     // also emits g_xb (bf16 x)
    // q,k rows of 1x1 conv (bf16 tensor path): [384,HW] = Wqk[384,192] @ xb[192,HW]
    gemm_bf16<<<dim3(6, 64, BATCH), 256>>>(wqkbp, xbp, qkbp);
    // v rows (tf32 path, A pre-converted): [192,HW] = Wv_t32[192,192] @ x[192,HW]
    gemm_mma<<<dim3(3, 64, BATCH), 256>>>(wvtp, x, vprep,
        CDIM, HW, CDIM, 0LL, (long long)CDIM*HW, (long long)CDIM*HW);
    k_dw_qkv<<<BATCH*C3, 256>>>(w_qkvdw);
    k_qk<<<dim3(64, 16), 144>>>();
    k_soft<<<dim3(HEADS, BATCH), 192>>>(temp, resc, w_proj);
    // final: out[b] = M_t32[b](192x192) @ V[b](192,HW)
    gemm_mma<<<dim3(3, 64, BATCH), 256>>>(Mp, vp, out,
        CDIM, HW, CDIM, (long long)CDIM*CDIM, (long long)CDIM*HW, (long long)CDIM*HW);
}

// round 14
// speedup vs baseline: 1.0511x; 1.0407x over previous
#include <cuda_runtime.h>
#include <cuda_bf16.h>
#include <cstdint>

#define HW   16384
#define CDIM 192
#define C3   576
#define BATCH 8
#define HEADS 8
#define CHD  24

typedef unsigned long long ull;

// ---------------- scratch (device globals: allocation-free rule) ----------------
__device__ __nv_bfloat16 g_xb [25165824];   // [8,192,16384] x in bf16 (for qk gemm)
__device__ __nv_bfloat16 g_wqkb[73728];     // [384,192] W_qkv rows 0..383 in bf16
__device__ float g_wvt [36864];             // [192,192] W_qkv v-rows, tf32-formatted
__device__ __nv_bfloat16 g_qkb[50331648];   // [8,384,16384] pre-conv q,k (bf16)
__device__ float g_vpre[25165824];          // [8,192,16384] pre-conv v (fp32)
__device__ __nv_bfloat16 g_qk[50331648];    // [8,384,16384] post-conv q,k (bf16)
__device__ float g_v  [25165824];           // [8,192,16384] post-conv v (fp32)
__device__ float g_var [BATCH*CDIM];
__device__ float g_norm[BATCH*384];
__device__ float g_S   [BATCH*HEADS*CHD*CHD];
__device__ float g_M   [BATCH*CDIM*CDIM];   // tf32-formatted by k_soft

__device__ __forceinline__ uint32_t smem_u32(const void* p) {
    uint32_t a;
    asm("{ .reg .u64 t; cvta.to.shared.u64 t, %1; cvt.u32.u64 %0, t; }" : "=r"(a) : "l"(p));
    return a;
}
__device__ __forceinline__ uint32_t f2tf32(float f) {
    uint32_t o;
    asm("cvt.rna.tf32.f32 %0, %1;" : "=r"(o) : "f"(f));
    return o;
}
__device__ __forceinline__ void mma_tf32(float* c, const uint32_t* a, const uint32_t* b) {
    asm("mma.sync.aligned.m16n8k8.row.col.f32.tf32.tf32.f32 "
        "{%0,%1,%2,%3}, {%4,%5,%6,%7}, {%8,%9}, {%0,%1,%2,%3};"
        : "+f"(c[0]), "+f"(c[1]), "+f"(c[2]), "+f"(c[3])
        : "r"(a[0]), "r"(a[1]), "r"(a[2]), "r"(a[3]), "r"(b[0]), "r"(b[1]));
}
__device__ __forceinline__ void mma_bf16(float* c, const uint32_t* a, const uint32_t* b) {
    asm("mma.sync.aligned.m16n8k16.row.col.f32.bf16.bf16.f32 "
        "{%0,%1,%2,%3}, {%4,%5,%6,%7}, {%8,%9}, {%0,%1,%2,%3};"
        : "+f"(c[0]), "+f"(c[1]), "+f"(c[2]), "+f"(c[3])
        : "r"(a[0]), "r"(a[1]), "r"(a[2]), "r"(a[3]), "r"(b[0]), "r"(b[1]));
}
__device__ __forceinline__ void ldsm_x4(uint32_t* r, uint32_t addr) {
    asm("ldmatrix.sync.aligned.m8n8.x4.shared.b16 {%0,%1,%2,%3}, [%4];"
        : "=r"(r[0]), "=r"(r[1]), "=r"(r[2]), "=r"(r[3]) : "r"(addr));
}
__device__ __forceinline__ void ldsm_x4t(uint32_t* r, uint32_t addr) {
    asm("ldmatrix.sync.aligned.m8n8.x4.trans.shared.b16 {%0,%1,%2,%3}, [%4];"
        : "=r"(r[0]), "=r"(r[1]), "=r"(r[2]), "=r"(r[3]) : "r"(addr));
}
__device__ __forceinline__ void cp_async16(uint32_t dst, const void* src) {
    asm volatile("cp.async.cg.shared.global [%0], [%1], 16;" :: "r"(dst), "l"(src) : "memory");
}
__device__ __forceinline__ ull pack2(float a, float b) {
    ull r; asm("mov.b64 %0, {%1,%2};" : "=l"(r) : "f"(a), "f"(b)); return r;
}
__device__ __forceinline__ void ffma2(ull& acc, ull a, ull b) {
    asm("fma.rn.f32x2 %0, %1, %2, %0;" : "+l"(acc) : "l"(a), "l"(b));
}
__device__ __forceinline__ void add2(ull& acc, ull a) {
    asm("add.rn.f32x2 %0, %0, %1;" : "+l"(acc) : "l"(a));
}
__device__ __forceinline__ float2 unpack2(ull v) {
    float2 o; asm("mov.b64 {%0,%1}, %2;" : "=f"(o.x), "=f"(o.y) : "l"(v)); return o;
}

// ================= bf16 mma GEMM for q,k rows: C[384,HW] = A[384,192] @ B[192,HW] =================
// BM=64, BN=256, BK=32, 3-stage cp.async pipeline, 256 threads.
__global__ void __launch_bounds__(256, 2) gemm_bf16(
    const __nv_bfloat16* __restrict__ A,
    const __nv_bfloat16* __restrict__ B,
    __nv_bfloat16* __restrict__ C)
{
    __shared__ __nv_bfloat16 As[3][64][40];
    __shared__ __nv_bfloat16 Bs[3][32][264];
    const int tid = threadIdx.x, lane = tid & 31, wid = tid >> 5;
    const int g = lane >> 2, t = lane & 3;
    const int bm = blockIdx.x * 64, bn = blockIdx.y * 256;
    const __nv_bfloat16* Bb = B + (size_t)blockIdx.z * CDIM * HW;
    __nv_bfloat16* Cb = C + (size_t)blockIdx.z * 384 * HW;

    const int arow = tid >> 2, akc = (tid & 3) * 8;

    float acc[4][4][4];
    #pragma unroll
    for (int i = 0; i < 4; i++)
        #pragma unroll
        for (int j = 0; j < 4; j++)
            #pragma unroll
            for (int l = 0; l < 4; l++) acc[i][j][l] = 0.f;

    const int a_m = (lane & 15);
    const int a_k = ((lane >> 4) & 1) * 8;
    const int b_k = (lane & 7) + ((lane >> 3) & 1) * 8;
    const int b_n = wid * 32 + ((lane >> 4) & 1) * 8;

    #pragma unroll
    for (int st = 0; st < 2; st++) {
        const int k0 = st * 32;
        cp_async16(smem_u32(&As[st][arow][akc]), &A[(size_t)(bm + arow) * 192 + k0 + akc]);
        #pragma unroll
        for (int p = 0; p < 4; p++) {
            int c = tid + p * 256;
            int kr = c >> 5, nc = (c & 31) * 8;
            cp_async16(smem_u32(&Bs[st][kr][nc]), &Bb[(size_t)(k0 + kr) * HW + bn + nc]);
        }
        asm volatile("cp.async.commit_group;" ::: "memory");
    }

    #pragma unroll 1
    for (int i = 0; i < 6; i++) {
        const int s = i % 3;
        if (i < 4) asm volatile("cp.async.wait_group 1;" ::: "memory");
        else       asm volatile("cp.async.wait_group 0;" ::: "memory");
        __syncthreads();
        if (i + 2 < 6) {
            const int sn = (i + 2) % 3;
            const int k0 = (i + 2) * 32;
            cp_async16(smem_u32(&As[sn][arow][akc]), &A[(size_t)(bm + arow) * 192 + k0 + akc]);
            #pragma unroll
            for (int p = 0; p < 4; p++) {
                int c = tid + p * 256;
                int kr = c >> 5, nc = (c & 31) * 8;
                cp_async16(smem_u32(&Bs[sn][kr][nc]), &Bb[(size_t)(k0 + kr) * HW + bn + nc]);
            }
            asm volatile("cp.async.commit_group;" ::: "memory");
        }
        #pragma unroll
        for (int kk = 0; kk < 2; kk++) {
            uint32_t af[4][4];
            #pragma unroll
            for (int ma = 0; ma < 4; ma++)
                ldsm_x4(af[ma], smem_u32(&As[s][ma * 16 + a_m][kk * 16 + a_k]));
            uint32_t bf[4][4];
            #pragma unroll
            for (int p = 0; p < 2; p++)
                ldsm_x4t(bf[p], smem_u32(&Bs[s][kk * 16 + b_k][b_n + p * 16]));
            #pragma unroll
            for (int ma = 0; ma < 4; ma++) {
                #pragma unroll
                for (int p = 0; p < 2; p++) {
                    mma_bf16(acc[ma][p * 2 + 0], af[ma], &bf[p][0]);
                    mma_bf16(acc[ma][p * 2 + 1], af[ma], &bf[p][2]);
                }
            }
        }
    }
    #pragma unroll
    for (int ma = 0; ma < 4; ma++) {
        #pragma unroll
        for (int nt = 0; nt < 4; nt++) {
            const int row = bm + ma * 16 + g;
            const int col = bn + wid * 32 + (nt >> 1) * 16 + (nt & 1) * 8 + 2 * t;
            __nv_bfloat162 h0 = __floats2bfloat162_rn(acc[ma][nt][0], acc[ma][nt][1]);
            __nv_bfloat162 h1 = __floats2bfloat162_rn(acc[ma][nt][2], acc[ma][nt][3]);
            *(__nv_bfloat162*)&Cb[(size_t)row * HW + col]       = h0;
            *(__nv_bfloat162*)&Cb[(size_t)(row + 8) * HW + col] = h1;
        }
    }
}

// ================= tf32 mma.sync GEMM, BN=256, BK=32, A pre-converted to tf32 =================
__global__ void __launch_bounds__(256, 2) gemm_mma(
    const float* __restrict__ A, const float* __restrict__ B, float* __restrict__ C,
    int M, int N, int K, long long sA, long long sB, long long sC)
{
    __shared__ float As[2][64][36];
    __shared__ float Bs[2][32][264];
    const int tid  = threadIdx.x;
    const int lane = tid & 31;
    const int wid  = tid >> 5;
    const int g    = lane >> 2;
    const int t    = lane & 3;
    const float* Ab = A + (long long)blockIdx.z * sA;
    const float* Bb = B + (long long)blockIdx.z * sB;
    float*       Cb = C + (long long)blockIdx.z * sC;
    const int bm = blockIdx.x * 64;
    const int bn = blockIdx.y * 256;

    const int arow = tid >> 2;
    const int acol = (tid & 3) * 8;
    const int a_m = lane & 15;
    const int a_k = (lane >> 4) * 4;

    float acc[4][4][4];
    #pragma unroll
    for (int i = 0; i < 4; i++)
        #pragma unroll
        for (int j = 0; j < 4; j++)
            #pragma unroll
            for (int l = 0; l < 4; l++) acc[i][j][l] = 0.f;

    cp_async16(smem_u32(&As[0][arow][acol]),     &Ab[(size_t)(bm + arow) * K + acol]);
    cp_async16(smem_u32(&As[0][arow][acol + 4]), &Ab[(size_t)(bm + arow) * K + acol + 4]);
    #pragma unroll
    for (int p = 0; p < 8; p++) {
        int c = tid + p * 256;
        int kr = c >> 6, nc = (c & 63) * 4;
        cp_async16(smem_u32(&Bs[0][kr][nc]), &Bb[(size_t)kr * N + bn + nc]);
    }
    asm volatile("cp.async.commit_group;" ::: "memory");
    asm volatile("cp.async.wait_group 0;" ::: "memory");
    __syncthreads();

    const int nchunk = K >> 5;
    #pragma unroll 1
    for (int i = 0; i < nchunk; i++) {
        const int s = i & 1;
        if (i + 1 < nchunk) {
            const int k0 = (i + 1) << 5;
            cp_async16(smem_u32(&As[s ^ 1][arow][acol]),     &Ab[(size_t)(bm + arow) * K + k0 + acol]);
            cp_async16(smem_u32(&As[s ^ 1][arow][acol + 4]), &Ab[(size_t)(bm + arow) * K + k0 + acol + 4]);
            #pragma unroll
            for (int p = 0; p < 8; p++) {
                int c = tid + p * 256;
                int kr = c >> 6, nc = (c & 63) * 4;
                cp_async16(smem_u32(&Bs[s ^ 1][kr][nc]), &Bb[(size_t)(k0 + kr) * N + bn + nc]);
            }
            asm volatile("cp.async.commit_group;" ::: "memory");
        }
        #pragma unroll
        for (int kk = 0; kk < 4; kk++) {
            uint32_t af[4][4];
            #pragma unroll
            for (int ma = 0; ma < 4; ma++)
                ldsm_x4(af[ma], smem_u32(&As[s][ma * 16 + a_m][kk * 8 + a_k]));
            uint32_t bf[4][2];
            #pragma unroll
            for (int na = 0; na < 4; na++) {
                bf[na][0] = f2tf32(Bs[s][kk * 8 + t    ][wid * 32 + na * 8 + g]);
                bf[na][1] = f2tf32(Bs[s][kk * 8 + t + 4][wid * 32 + na * 8 + g]);
            }
            #pragma unroll
            for (int ma = 0; ma < 4; ma++)
                #pragma unroll
                for (int na = 0; na < 4; na++)
                    mma_tf32(acc[ma][na], af[ma], bf[na]);
        }
        if (i + 1 < nchunk) asm volatile("cp.async.wait_group 0;" ::: "memory");
        __syncthreads();
    }
    #pragma unroll
    for (int ma = 0; ma < 4; ma++) {
        #pragma unroll
        for (int na = 0; na < 4; na++) {
            const int row = bm + ma * 16 + g;
            const int col = bn + wid * 32 + na * 8 + (t << 1);
            *(float2*)&Cb[(size_t)row * N + col]       = make_float2(acc[ma][na][0], acc[ma][na][1]);
            *(float2*)&Cb[(size_t)(row + 8) * N + col] = make_float2(acc[ma][na][2], acc[ma][na][3]);
        }
    }
}

// ---------------- zero S + convert qk-weights to bf16 + v-weights to tf32 ----------------
__global__ void k_zero(const float* __restrict__ w_qkv) {
    int i = blockIdx.x * blockDim.x + threadIdx.x;
    if (i < BATCH*HEADS*CHD*CHD) g_S[i] = 0.f;
    if (i < 384*CDIM) g_wqkb[i] = __float2bfloat16(w_qkv[i]);
    if (i < CDIM*CDIM) g_wvt[i] = __uint_as_float(f2tf32(w_qkv[384*CDIM + i]));
}

// =============== rolling-window f32x2 depthwise 3x3 core pieces ===============
__device__ __forceinline__ void conv_loadP(const float* s, int sr, int x4, int lane, ull* P) {
    const float* rp = &s[sr * 132 + x4];
    float4 q = *(const float4*)rp;
    float rx = rp[4];
    float lf = __shfl_up_sync(0xffffffffu, q.w, 1);
    if (lane == 0) lf = 0.f;
    P[0] = pack2(lf,  q.x);
    P[1] = pack2(q.x, q.y);
    P[2] = pack2(q.y, q.z);
    P[3] = pack2(q.z, q.w);
    P[4] = pack2(q.w, rx);
}

#define CONV_ACC(a01, a23, P, o, Wp)                                        \
    {                                                                        \
        _Pragma("unroll")                                                    \
        for (int r = 0; r < 3; r++) {                                        \
            const ull* Q = P[((o) + r) % 3];                                 \
            ffma2(a01, Q[0], Wp[3*r+0]); ffma2(a01, Q[1], Wp[3*r+1]);        \
            ffma2(a01, Q[2], Wp[3*r+2]);                                     \
            ffma2(a23, Q[2], Wp[3*r+0]); ffma2(a23, Q[3], Wp[3*r+1]);        \
            ffma2(a23, Q[4], Wp[3*r+2]);                                     \
        }                                                                    \
    }

// ---------------- depthwise 3x3 on x + variance + x->bf16 emit ----------------
__global__ __launch_bounds__(256) void k_dw_var(const float* __restrict__ x,
                                                const float* __restrict__ wdw)
{
    __shared__ float s[66*132];
    __shared__ float red[64];
    const int bc = blockIdx.x;
    const float* plane = x + (size_t)bc * HW;
    __nv_bfloat16* xbp = g_xb + (size_t)bc * HW;
    const int c = bc % CDIM;
    const int tid = threadIdx.x;
    const int lane = tid & 31;
    const int strip = tid >> 5;
    const int x4 = lane << 2;
    ull Wp[9];
    #pragma unroll
    for (int i = 0; i < 9; i++) { float w = wdw[c*9 + i]; Wp[i] = pack2(w, w); }
    ull accS = 0ull, accQ = 0ull;

    for (int half = 0; half < 2; half++) {
        if (half) __syncthreads();
        const int y0 = half * 64;
        for (int i = tid; i < 66*32; i += 256) {
            int r = i >> 5, j4 = (i & 31) << 2;
            int y = y0 + r - 1;
            float4 v = make_float4(0.f, 0.f, 0.f, 0.f);
            if ((unsigned)y < 128u) v = *(const float4*)&plane[y*128 + j4];
            *(float4*)&s[r*132 + j4] = v;
            if (r >= 1 && r <= 64 && (unsigned)y < 128u) {
                __nv_bfloat162 h0 = __floats2bfloat162_rn(v.x, v.y);
                __nv_bfloat162 h1 = __floats2bfloat162_rn(v.z, v.w);
                uint2 u; u.x = *(uint32_t*)&h0; u.y = *(uint32_t*)&h1;
                *(uint2*)&xbp[y*128 + j4] = u;
            }
        }
        for (int i = tid; i < 66; i += 256) { s[i*132+128] = 0.f; s[i*132+129] = 0.f; }
        __syncthreads();

        ull P[3][5];
        const int base = strip * 8;
        conv_loadP(s, base,     x4, lane, P[0]);
        conv_loadP(s, base + 1, x4, lane, P[1]);
        #pragma unroll
        for (int o = 0; o < 8; o++) {
            conv_loadP(s, base + o + 2, x4, lane, P[(o + 2) % 3]);
            ull a01 = 0ull, a23 = 0ull;
            CONV_ACC(a01, a23, P, o, Wp);
            add2(accS, a01); add2(accS, a23);
            ffma2(accQ, a01, a01); ffma2(accQ, a23, a23);
        }
    }
    float2 S2 = unpack2(accS), Q2 = unpack2(accQ);
    float sum = S2.x + S2.y, sq = Q2.x + Q2.y;
    #pragma unroll
    for (int o = 16; o > 0; o >>= 1) {
        sum += __shfl_down_sync(0xffffffffu, sum, o);
        sq  += __shfl_down_sync(0xffffffffu, sq,  o);
    }
    if (lane == 0) { red[strip] = sum; red[32 + strip] = sq; }
    __syncthreads();
    if (tid == 0) {
        float S = 0.f, Q = 0.f;
        #pragma unroll
        for (int i = 0; i < 8; i++) { S += red[i]; Q += red[32+i]; }
        g_var[bc] = (Q - S*S*(1.f/16384.f)) * (1.f/16383.f);
    }
}

// ---------------- depthwise 3x3 on qkv channels [chbase, chbase+nch) ----------------
// q,k channels -> bf16 out + norms; v channels -> fp32 out.
__global__ __launch_bounds__(256) void k_dw_qkv(const float* __restrict__ wdw,
                                                int chbase, int nch)
{
    __shared__ float s[66*132];
    __shared__ float red[8];
    const int b  = blockIdx.x / nch;
    const int ch = chbase + (blockIdx.x % nch);
    const bool is_qk = ch < 384;
    const __nv_bfloat16* planeb = g_qkb + ((size_t)b*384 + ch) * HW;
    const float*         planef = g_vpre + ((size_t)b*CDIM + (ch - 384)) * HW;
    __nv_bfloat16* outb = g_qk + ((size_t)b*384 + ch) * HW;
    float*         outv = g_v  + ((size_t)b*CDIM + (ch - 384)) * HW;
    const int tid = threadIdx.x;
    const int lane = tid & 31;
    const int strip = tid >> 5;
    const int x4 = lane << 2;
    ull Wp[9];
    #pragma unroll
    for (int i = 0; i < 9; i++) { float w = wdw[ch*9 + i]; Wp[i] = pack2(w, w); }
    float sq = 0.f;

    for (int half = 0; half < 2; half++) {
        if (half) __syncthreads();
        const int y0 = half * 64;
        if (is_qk) {
            for (int i = tid; i < 66*32; i += 256) {
                int r = i >> 5, j4 = (i & 31) << 2;
                int y = y0 + r - 1;
                float4 v = make_float4(0.f, 0.f, 0.f, 0.f);
                if ((unsigned)y < 128u) {
                    uint2 u = *(const uint2*)&planeb[y*128 + j4];
                    float2 f0 = __bfloat1622float2(*(__nv_bfloat162*)&u.x);
                    float2 f1 = __bfloat1622float2(*(__nv_bfloat162*)&u.y);
                    v = make_float4(f0.x, f0.y, f1.x, f1.y);
                }
                *(float4*)&s[r*132 + j4] = v;
            }
        } else {
            for (int i = tid; i < 66*32; i += 256) {
                int r = i >> 5, j4 = (i & 31) << 2;
                int y = y0 + r - 1;
                float4 v = make_float4(0.f, 0.f, 0.f, 0.f);
                if ((unsigned)y < 128u) v = *(const float4*)&planef[y*128 + j4];
                *(float4*)&s[r*132 + j4] = v;
            }
        }
        for (int i = tid; i < 66; i += 256) { s[i*132+128] = 0.f; s[i*132+129] = 0.f; }
        __syncthreads();

        ull P[3][5];
        const int base = strip * 8;
        conv_loadP(s, base,     x4, lane, P[0]);
        conv_loadP(s, base + 1, x4, lane, P[1]);
        #pragma unroll
        for (int o = 0; o < 8; o++) {
            conv_loadP(s, base + o + 2, x4, lane, P[(o + 2) % 3]);
            ull a01 = 0ull, a23 = 0ull;
            CONV_ACC(a01, a23, P, o, Wp);
            const int y = y0 + base + o;
            float2 v01 = unpack2(a01), v23 = unpack2(a23);
            if (is_qk) {
                __nv_bfloat162 h0 = __floats2bfloat162_rn(v01.x, v01.y);
                __nv_bfloat162 h1 = __floats2bfloat162_rn(v23.x, v23.y);
                uint2 st;
                st.x = *(uint32_t*)&h0; st.y = *(uint32_t*)&h1;
                *(uint2*)&outb[y*128 + x4] = st;
                float2 r0 = __bfloat1622float2(h0), r1 = __bfloat1622float2(h1);
                sq += r0.x*r0.x + r0.y*r0.y + r1.x*r1.x + r1.y*r1.y;
            } else {
                *(float4*)&outv[y*128 + x4] = make_float4(v01.x, v01.y, v23.x, v23.y);
            }
        }
    }
    if (is_qk) {
        #pragma unroll
        for (int o = 16; o > 0; o >>= 1) sq += __shfl_down_sync(0xffffffffu, sq, o);
        if (lane == 0) red[strip] = sq;
        __syncthreads();
        if (tid == 0) {
            float Q = 0.f;
            #pragma unroll
            for (int i = 0; i < 8; i++) Q += red[i];
            g_norm[b*384 + ch] = Q;
        }
    }
}

// ---------------- S = q @ k^T per (b,h) from bf16, split-K with atomics ----------------
__global__ __launch_bounds__(144) void k_qk()
{
    __shared__ float qs[24][64];
    __shared__ float ks[24][64];
    const int bh = blockIdx.x;
    const int b = bh >> 3, h = bh & 7;
    const __nv_bfloat16* qb = g_qk + ((size_t)b*384 + h*CHD) * HW;
    const __nv_bfloat16* kb = g_qk + ((size_t)b*384 + 192 + h*CHD) * HW;
    const int n0 = blockIdx.y * 1024;
    const int tid = threadIdx.x;
    const int sub = tid & 3;
    const int cd  = tid >> 2;
    const int c0 = (cd / 6) * 4, d0 = (cd % 6) * 4;
    float acc[4][4] = {};
    for (int chk = 0; chk < 16; chk++) {
        if (chk) __syncthreads();
        const int nn = n0 + chk * 64;
        for (int i = tid; i < 24*32; i += 144) {
            int r = i >> 5, j2 = (i & 31) << 1;
            __nv_bfloat162 q2 = *(const __nv_bfloat162*)&qb[(size_t)r*HW + nn + j2];
            __nv_bfloat162 k2 = *(const __nv_bfloat162*)&kb[(size_t)r*HW + nn + j2];
            *(float2*)&qs[r][j2] = __bfloat1622float2(q2);
            *(float2*)&ks[r][j2] = __bfloat1622float2(k2);
        }
        __syncthreads();
        const int j0 = sub * 16;
        #pragma unroll 4
        for (int j = j0; j < j0 + 16; j++) {
            float q0 = qs[c0+0][j], q1 = qs[c0+1][j], q2 = qs[c0+2][j], q3 = qs[c0+3][j];
            float k0 = ks[d0+0][j], k1 = ks[d0+1][j], k2 = ks[d0+2][j], k3 = ks[d0+3][j];
            acc[0][0] += q0*k0; acc[0][1] += q0*k1; acc[0][2] += q0*k2; acc[0][3] += q0*k3;
            acc[1][0] += q1*k0; acc[1][1] += q1*k1; acc[1][2] += q1*k2; acc[1][3] += q1*k3;
            acc[2][0] += q2*k0; acc[2][1] += q2*k1; acc[2][2] += q2*k2; acc[2][3] += q2*k3;
            acc[3][0] += q3*k0; acc[3][1] += q3*k1; acc[3][2] += q3*k2; acc[3][3] += q3*k3;
        }
    }
    #pragma unroll
    for (int i = 0; i < 4; i++)
        #pragma unroll
        for (int l = 0; l < 4; l++)
            atomicAdd(&g_S[(size_t)bh*576 + (c0+i)*24 + (d0+l)], acc[i][l]);
}

// ---------------- softmax + M = Wproj @ blockdiag(attn), M emitted tf32-formatted ----------------
__global__ __launch_bounds__(192) void k_soft(const float* __restrict__ temp,
                                              const float* __restrict__ resc,
                                              const float* __restrict__ wproj)
{
    __shared__ float a[24][24];
    const int h = blockIdx.x, b = blockIdx.y;
    const int tid = threadIdx.x;
    const float* Sp = g_S + (size_t)(b*8 + h) * 576;
    const float t = temp[h];
    for (int idx = tid; idx < 576; idx += 192) {
        int c = idx / 24, d = idx % 24;
        float nq = sqrtf(g_norm[b*384 + h*24 + c]);
        float nk = sqrtf(g_norm[b*384 + 192 + h*24 + d]);
        float denom = fmaxf(nq, 1e-12f) * fmaxf(nk, 1e-12f);
        float l = Sp[idx] / denom * t;
        if (c == d) l += resc[h] * g_var[b*192 + h*24 + c];
        a[c][d] = l;
    }
    __syncthreads();
    if (tid < 24) {
        const int c = tid;
        float m = -1e30f;
        #pragma unroll
        for (int d = 0; d < 24; d++) m = fmaxf(m, a[c][d]);
        float e[24]; float ssum = 0.f;
        #pragma unroll
        for (int d = 0; d < 24; d++) { e[d] = expf(a[c][d] - m); ssum += e[d]; }
        float inv = 1.f / ssum;
        #pragma unroll
        for (int d = 0; d < 24; d++) a[c][d] = e[d] * inv;
    }
    __syncthreads();
    const int co = tid;
    float wr[24];
    #pragma unroll
    for (int c = 0; c < 24; c++) wr[c] = wproj[(size_t)co*CDIM + h*24 + c];
    float* Mp = g_M + (size_t)b*CDIM*CDIM + (size_t)co*CDIM + h*24;
    #pragma unroll 4
    for (int d = 0; d < 24; d++) {
        float accv = 0.f;
        #pragma unroll
        for (int c = 0; c < 24; c++) accv += wr[c] * a[c][d];
        Mp[d] = __uint_as_float(f2tf32(accv));
    }
}

// ---------------- launch (multi-stream graph fork) ----------------
extern "C" void kernel_launch(void* const* d_in, const int* in_sizes, int n_in,
                              void* d_out, int out_size)
{
    const float* x       = (const float*)d_in[0];
    const float* w_dw    = (const float*)d_in[1];
    const float* w_qkv   = (const float*)d_in[2];
    const float* w_qkvdw = (const float*)d_in[3];
    const float* w_proj  = (const float*)d_in[4];
    const float* temp    = (const float*)d_in[5];
    const float* resc    = (const float*)d_in[6];
    float* out = (float*)d_out;

    float *vprep, *vp, *Mp, *wvtp;
    __nv_bfloat16 *qkbp, *xbp, *wqkbp;
    cudaGetSymbolAddress((void**)&qkbp,  g_qkb);
    cudaGetSymbolAddress((void**)&xbp,   g_xb);
    cudaGetSymbolAddress((void**)&wqkbp, g_wqkb);
    cudaGetSymbolAddress((void**)&wvtp,  g_wvt);
    cudaGetSymbolAddress((void**)&vprep, g_vpre);
    cudaGetSymbolAddress((void**)&vp,    g_v);
    cudaGetSymbolAddress((void**)&Mp,    g_M);

    cudaFuncSetAttribute(gemm_mma,  cudaFuncAttributePreferredSharedMemoryCarveout, 90);
    cudaFuncSetAttribute(gemm_bf16, cudaFuncAttributePreferredSharedMemoryCarveout, 90);

    // side stream + fork/join events (created once; capture-legal thereafter)
    static cudaStream_t s2 = [] {
        cudaStream_t s; cudaStreamCreateWithFlags(&s, cudaStreamNonBlocking); return s;
    }();
    static cudaEvent_t evA = [] {
        cudaEvent_t e; cudaEventCreateWithFlags(&e, cudaEventDisableTiming); return e;
    }();
    static cudaEvent_t evB = [] {
        cudaEvent_t e; cudaEventCreateWithFlags(&e, cudaEventDisableTiming); return e;
    }();

    // main stream: prologue
    k_zero<<<72, 1024>>>(w_qkv);
    cudaEventRecord(evA, 0);

    // side stream: v-path (needs only k_zero + x)
    cudaStreamWaitEvent(s2, evA, 0);
    gemm_mma<<<dim3(3, 64, BATCH), 256, 0, s2>>>(wvtp, x, vprep,
        CDIM, HW, CDIM, 0LL, (long long)CDIM*HW, (long long)CDIM*HW);
    k_dw_qkv<<<BATCH*192, 256, 0, s2>>>(w_qkvdw, 384, 192);   // v channels -> g_v
    cudaEventRecord(evB, s2);

    // main stream: qk-path
    k_dw_var<<<BATCH*CDIM, 256>>>(x, w_dw);                   // g_var + g_xb
    gemm_bf16<<<dim3(6, 64, BATCH), 256>>>(wqkbp, xbp, qkbp); // pre-conv q,k
    k_dw_qkv<<<BATCH*384, 256>>>(w_qkvdw, 0, 384);            // qk channels -> g_qk + norms
    k_qk<<<dim3(64, 16), 144>>>();
    k_soft<<<dim3(HEADS, BATCH), 192>>>(temp, resc, w_proj);

    // join: gemm2 needs g_M (main) + g_v (side)
    cudaStreamWaitEvent(0, evB, 0);
    gemm_mma<<<dim3(3, 64, BATCH), 256>>>(Mp, vp, out,
        CDIM, HW, CDIM, (long long)CDIM*CDIM, (long long)CDIM*HW, (long long)CDIM*HW);
}